// round 7
// baseline (speedup 1.0000x reference)
#include <cuda_runtime.h>
#include <cuda_fp16.h>
#include <cstdint>

#define B_    8
#define C_    128
#define N_    4096
#define M_    4096
#define OUT_  128
#define LOG2E 1.4426950408889634f

// single shared-mem declaration for the whole TU (nvcc requires consistency)
extern __shared__ char dyn_smem[];

// ---------------------------------------------------------------------------
// static device scratch (allocation-free)
// ---------------------------------------------------------------------------
__device__ __half g_qh[(size_t)B_ * M_ * C_];   // [b][m][c] normalized*log2e (fp16)
__device__ __half g_kh[(size_t)B_ * N_ * C_];   // [b][n][c] normalized hi
__device__ __half g_kl[(size_t)B_ * N_ * C_];   // residual
__device__ __half g_vh[(size_t)B_ * C_ * N_];   // [b][c][n] raw fp16
__device__ float  g_agg[(size_t)B_ * M_ * C_];  // [b][m][c]

// ---------------------------------------------------------------------------
// helpers (base-ISA only: ldmatrix / mma.sync / cp.async)
// ---------------------------------------------------------------------------
__device__ __forceinline__ uint32_t smem_u32(const void* p) {
    uint32_t a;
    asm("{ .reg .u64 t; cvta.to.shared.u64 t, %1; cvt.u32.u64 %0, t; }" : "=r"(a) : "l"(p));
    return a;
}
__device__ __forceinline__ void ldsm4(uint32_t* r, uint32_t addr) {
    asm volatile("ldmatrix.sync.aligned.m8n8.x4.shared.b16 {%0,%1,%2,%3}, [%4];"
                 : "=r"(r[0]), "=r"(r[1]), "=r"(r[2]), "=r"(r[3]) : "r"(addr));
}
__device__ __forceinline__ void mma16816(float* d, const uint32_t* a, const uint32_t* b) {
    asm volatile("mma.sync.aligned.m16n8k16.row.col.f32.f16.f16.f32 "
                 "{%0,%1,%2,%3}, {%4,%5,%6,%7}, {%8,%9}, {%0,%1,%2,%3};"
                 : "+f"(d[0]), "+f"(d[1]), "+f"(d[2]), "+f"(d[3])
                 : "r"(a[0]), "r"(a[1]), "r"(a[2]), "r"(a[3]), "r"(b[0]), "r"(b[1]));
}
__device__ __forceinline__ void cpasync16(uint32_t saddr, const void* gaddr) {
    asm volatile("cp.async.cg.shared.global [%0], [%1], 16;" :: "r"(saddr), "l"(gaddr));
}
#define CP_COMMIT() asm volatile("cp.async.commit_group;" ::: "memory")
#define CP_WAIT1()  asm volatile("cp.async.wait_group 1;" ::: "memory")
__device__ __forceinline__ float fast_exp2(float x) {
    float r;
    asm("ex2.approx.ftz.f32 %0, %1;" : "=f"(r) : "f"(x));
    return r;
}
__device__ __forceinline__ uint32_t pack_h2(float lo, float hi) {
    __half2 h = __floats2half2_rn(lo, hi);   // lo -> low 16 bits
    return *(uint32_t*)&h;
}

// ---------------------------------------------------------------------------
// prep: normalize over C, transpose to [b][l][c], fp16 (hi [+ residual lo])
// ---------------------------------------------------------------------------
__global__ __launch_bounds__(256, 1)
void prep_qk(const float* __restrict__ x, __half* __restrict__ hi_out,
             __half* __restrict__ lo_out, float extra_scale) {
    float* t  = (float*)dyn_smem;              // [128][129]
    float* rn = t + 128 * 129;
    int blk = blockIdx.x;
    int b = blk >> 5, l0 = (blk & 31) * 128;
    int tid = threadIdx.x;
    const float* src = x + (size_t)b * C_ * 4096 + l0;
    for (int idx = tid; idx < 128 * 128; idx += 256) {
        int c = idx >> 7, l = idx & 127;
        t[c * 129 + l] = src[(size_t)c * 4096 + l];
    }
    __syncthreads();
    if (tid < 128) {
        float s = 0.f;
#pragma unroll 8
        for (int c = 0; c < 128; c++) { float v = t[c * 129 + tid]; s += v * v; }
        rn[tid] = extra_scale / fmaxf(sqrtf(s), 1e-12f);
    }
    __syncthreads();
    for (int idx = tid; idx < 128 * 128; idx += 256) {
        int l = idx >> 7, c = idx & 127;
        float v = t[c * 129 + l] * rn[l];
        __half h = __float2half_rn(v);
        size_t o = ((size_t)b * 4096 + l0 + l) * C_ + c;
        hi_out[o] = h;
        if (lo_out) lo_out[o] = __float2half_rn(v - __half2float(h));
    }
}

__global__ void prep_v(const float* __restrict__ x) {
    size_t i = (size_t)blockIdx.x * 256 + threadIdx.x;
    if (i >= (size_t)B_ * C_ * N_ / 4) return;
    float4 v = ((const float4*)x)[i];
    ((uint2*)g_vh)[i] = make_uint2(pack_h2(v.x, v.y), pack_h2(v.z, v.w));
}

// ---------------------------------------------------------------------------
// HMMA fp16 flash attention. grid = B*(M/64)=512, 128 threads (4 warps),
// 2 CTAs/SM. Rotating single-buffer K/V pipeline via cp.async groups.
// smem: Q 16K | Kh 16K | Kl 16K | Vh 16K  = 64K
// ---------------------------------------------------------------------------
#define SMQ  0
#define SMKH 16384
#define SMKL 32768
#define SMV  49152
#define ATTN_SMEM 65536

__global__ __launch_bounds__(128, 2)
void attn_mma_kernel() {
    char* smc = dyn_smem;
    uint32_t sbase = smem_u32(smc);

    int tid = threadIdx.x;
    int w = tid >> 5, ln = tid & 31;
    int b  = blockIdx.x >> 6;
    int m0 = (blockIdx.x & 63) * 64;

    // ---- load Q tile [64m][128c] (once, plain stores) ----
    {
        const uint4* qg = (const uint4*)(g_qh + ((size_t)b * M_ + m0) * C_);
        for (int idx = tid; idx < 1024; idx += 128) {
            int row = idx >> 4, ch = idx & 15;
            uint32_t off = row * 256 + ((ch ^ (row & 7)) << 4);
            *(uint4*)(smc + SMQ + off) = qg[row * 16 + ch];
        }
    }

    auto issue_K = [&](int it) {
        int n0 = it * 64;
        const char* khg = (const char*)(g_kh + ((size_t)b * N_ + n0) * C_);
        const char* klg = (const char*)(g_kl + ((size_t)b * N_ + n0) * C_);
#pragma unroll
        for (int i = 0; i < 8; i++) {
            int idx = tid + i * 128;
            int row = idx >> 4, ch = idx & 15;
            uint32_t off = row * 256 + ((ch ^ (row & 7)) << 4);
            cpasync16(sbase + SMKH + off, khg + row * 256 + ch * 16);
            cpasync16(sbase + SMKL + off, klg + row * 256 + ch * 16);
        }
    };
    auto issue_V = [&](int it) {
        int n0 = it * 64;
        const char* vhg = (const char*)(g_vh + (size_t)b * C_ * N_ + n0);
#pragma unroll
        for (int i = 0; i < 8; i++) {
            int idx = tid + i * 128;
            int row = idx >> 3, ch = idx & 7;
            uint32_t off = row * 128 + ((ch ^ (row & 7)) << 4);
            cpasync16(sbase + SMV + off, vhg + (size_t)row * 8192 + ch * 16);
        }
    };

    float oacc[16][4];
#pragma unroll
    for (int i = 0; i < 16; i++)
#pragma unroll
        for (int j = 0; j < 4; j++) oacc[i][j] = 0.f;
    float rs0 = 0.f, rs1 = 0.f;

    issue_K(0); CP_COMMIT();      // group: K0
    issue_V(0); CP_COMMIT();      // group: V0

    for (int it = 0; it < 64; it++) {
        CP_WAIT1();               // K_it landed (V_it may still be in flight)
        __syncthreads();

        // ---- S = Q.K^T  (Qh*Kh + Qh*Kl) ----
        float sacc[8][4];
#pragma unroll
        for (int i = 0; i < 8; i++)
#pragma unroll
            for (int j = 0; j < 4; j++) sacc[i][j] = 0.f;

#pragma unroll
        for (int ks = 0; ks < 8; ks++) {
            uint32_t qh[4];
            {
                int r = 16 * w + (ln & 15);
                int ch = 2 * ks + (ln >> 4);
                uint32_t off = r * 256 + ((ch ^ (r & 7)) << 4);
                ldsm4(qh, sbase + SMQ + off);
            }
            uint32_t bh[4][4], bl[4][4];
#pragma unroll
            for (int p = 0; p < 4; p++) {
                int r = 16 * p + ((ln >> 4) << 3) + (ln & 7);
                int ch = 2 * ks + ((ln >> 3) & 1);
                uint32_t off = r * 256 + ((ch ^ (r & 7)) << 4);
                ldsm4(bh[p], sbase + SMKH + off);
                ldsm4(bl[p], sbase + SMKL + off);
            }
#pragma unroll
            for (int p = 0; p < 4; p++) { mma16816(sacc[2*p], qh, bh[p]); mma16816(sacc[2*p+1], qh, bh[p]+2); }
#pragma unroll
            for (int p = 0; p < 4; p++) { mma16816(sacc[2*p], qh, bl[p]); mma16816(sacc[2*p+1], qh, bl[p]+2); }
        }

        __syncthreads();          // all warps done reading K buffer
        if (it + 1 < 64) issue_K(it + 1);
        CP_COMMIT();              // group: K_{it+1} (lands during softmax + O phase)

        // ---- P = exp2(S) (max-free: scores bounded), fp16 pack, rowsum ----
        uint32_t phi[8][2];
#pragma unroll
        for (int nb = 0; nb < 8; nb++) {
            float p0 = fast_exp2(sacc[nb][0]);
            float p1 = fast_exp2(sacc[nb][1]);
            float p2 = fast_exp2(sacc[nb][2]);
            float p3 = fast_exp2(sacc[nb][3]);
            rs0 += p0 + p1;
            rs1 += p2 + p3;
            phi[nb][0] = pack_h2(p0, p1);
            phi[nb][1] = pack_h2(p2, p3);
        }

        CP_WAIT1();               // V_it landed (K_{it+1} may still be in flight)
        __syncthreads();

        // ---- O += P.V^T  (Ph*Vh) ----
#pragma unroll
        for (int kn = 0; kn < 4; kn++) {
            uint32_t ah[4] = {phi[2*kn][0], phi[2*kn][1], phi[2*kn+1][0], phi[2*kn+1][1]};
#pragma unroll
            for (int g = 0; g < 2; g++) {
                uint32_t vh[4][4];
#pragma unroll
                for (int p = 0; p < 4; p++) {
                    int r = 16 * (4 * g + p) + ((ln >> 4) << 3) + (ln & 7);
                    int ch = 2 * kn + ((ln >> 3) & 1);
                    uint32_t off = r * 128 + ((ch ^ (r & 7)) << 4);
                    ldsm4(vh[p], sbase + SMV + off);
                }
#pragma unroll
                for (int p = 0; p < 4; p++) { int cb = 8*g + 2*p; mma16816(oacc[cb], ah, vh[p]); mma16816(oacc[cb+1], ah, vh[p]+2); }
            }
        }

        __syncthreads();          // all warps done reading V buffer
        if (it + 1 < 64) issue_V(it + 1);
        CP_COMMIT();              // group: V_{it+1}
    }

    // ---- finalize: divide by row sums, store [b][m][c] ----
    rs0 += __shfl_xor_sync(0xffffffffu, rs0, 1);
    rs0 += __shfl_xor_sync(0xffffffffu, rs0, 2);
    rs1 += __shfl_xor_sync(0xffffffffu, rs1, 1);
    rs1 += __shfl_xor_sync(0xffffffffu, rs1, 2);
    float inv0 = 1.0f / rs0, inv1 = 1.0f / rs1;

    float* dst = g_agg + ((size_t)(b * M_ + m0 + 16 * w + (ln >> 2))) * C_ + 2 * (ln & 3);
#pragma unroll
    for (int cb = 0; cb < 16; cb++) {
        *(float2*)(dst + 8 * cb)          = make_float2(oacc[cb][0] * inv0, oacc[cb][1] * inv0);
        *(float2*)(dst + 8 * C_ + 8 * cb) = make_float2(oacc[cb][2] * inv1, oacc[cb][3] * inv1);
    }
}

// ---------------------------------------------------------------------------
// epilogue: out[b][o][m] = BN(LeakyReLU(agg[b][m][:] . W[:,o]))
// OUT split in halves per CTA for occupancy (3 CTAs/SM).
// grid = B*(M/64)*2 = 1024, 256 threads (16x16), microtile 4m x 4o
// ---------------------------------------------------------------------------
#define TM 64
#define A_LD 132
#define OH 64
#define THREADS 256
__global__ __launch_bounds__(THREADS)
void epi_kernel(const float* __restrict__ w,
                const float* __restrict__ gamma,
                const float* __restrict__ beta,
                const float* __restrict__ rmean,
                const float* __restrict__ rvar,
                float* __restrict__ out) {
    float* ws = (float*)dyn_smem;        // [128][64]
    float* as = ws + C_ * OH;            // [64][132]
    float* sc = as + TM * A_LD;          // [64]
    float* bi = sc + OH;                 // [64]

    int bm = blockIdx.x;
    int half = bm & 1;
    int rest = bm >> 1;
    int b  = rest >> 6;
    int m0 = (rest & 63) * TM;
    int o0 = half * OH;
    int tid = threadIdx.x;
    int tx = tid & 15, ty = tid >> 4;

    for (int idx = tid; idx < C_ * (OH / 4); idx += THREADS) {
        int c = idx >> 4, o4 = idx & 15;
        *(float4*)&ws[c * OH + 4 * o4] = *(const float4*)&w[c * OUT_ + o0 + 4 * o4];
    }
    for (int idx = tid; idx < TM * (C_ / 4); idx += THREADS) {
        int m = idx >> 5, c4 = idx & 31;
        float4 v = *(const float4*)&g_agg[((size_t)(b * M_ + m0 + m)) * C_ + 4 * c4];
        *(float4*)&as[m * A_LD + 4 * c4] = v;
    }
    if (tid < OH) {
        int o = o0 + tid;
        float s = rsqrtf(rvar[o] + 1e-5f) * gamma[o];
        sc[tid] = s;
        bi[tid] = beta[o] - rmean[o] * s;
    }
    __syncthreads();

    float acc[4][4];
#pragma unroll
    for (int r = 0; r < 4; r++)
#pragma unroll
        for (int j = 0; j < 4; j++) acc[r][j] = 0.f;

    for (int c = 0; c < C_; c += 4) {
        float areg[4][4];
#pragma unroll
        for (int r = 0; r < 4; r++) {
            float4 t = *(const float4*)&as[(4 * ty + r) * A_LD + c];
            areg[r][0] = t.x; areg[r][1] = t.y; areg[r][2] = t.z; areg[r][3] = t.w;
        }
#pragma unroll
        for (int cc = 0; cc < 4; cc++) {
            float4 wv = *(const float4*)&ws[(c + cc) * OH + 4 * tx];
            float wa[4] = {wv.x, wv.y, wv.z, wv.w};
#pragma unroll
            for (int r = 0; r < 4; r++)
#pragma unroll
                for (int j = 0; j < 4; j++)
                    acc[r][j] += areg[r][cc] * wa[j];
        }
    }
#pragma unroll
    for (int r = 0; r < 4; r++) {
        int m = m0 + 4 * ty + r;
#pragma unroll
        for (int j = 0; j < 4; j++) {
            int ol = 4 * tx + j;
            float z = acc[r][j];
            z = (z >= 0.f) ? z : 0.01f * z;
            out[((size_t)b * OUT_ + o0 + ol) * M_ + m] = z * sc[ol] + bi[ol];
        }
    }
}

// ---------------------------------------------------------------------------
extern "C" void kernel_launch(void* const* d_in, const int* in_sizes, int n_in,
                              void* d_out, int out_size) {
    const float* input  = (const float*)d_in[0];
    const float* tg     = (const float*)d_in[1];
    const float* weight = (const float*)d_in[2];
    const float* gamma  = (const float*)d_in[3];
    const float* beta   = (const float*)d_in[4];
    const float* rmean  = (const float*)d_in[5];
    const float* rvar   = (const float*)d_in[6];
    float* out = (float*)d_out;

    __half *p_qh, *p_kh, *p_kl;
    cudaGetSymbolAddress((void**)&p_qh, g_qh);
    cudaGetSymbolAddress((void**)&p_kh, g_kh);
    cudaGetSymbolAddress((void**)&p_kl, g_kl);

    const int prep_smem = (128 * 129 + 128) * (int)sizeof(float);
    const int epi_smem  = (C_ * OH + TM * A_LD + 2 * OH) * (int)sizeof(float);
    cudaFuncSetAttribute(prep_qk, cudaFuncAttributeMaxDynamicSharedMemorySize, prep_smem);
    cudaFuncSetAttribute(attn_mma_kernel, cudaFuncAttributeMaxDynamicSharedMemorySize, ATTN_SMEM);
    cudaFuncSetAttribute(epi_kernel, cudaFuncAttributeMaxDynamicSharedMemorySize, epi_smem);

    prep_qk<<<B_ * (M_ / 128), 256, prep_smem>>>(tg,    p_qh, nullptr, LOG2E);
    prep_qk<<<B_ * (N_ / 128), 256, prep_smem>>>(input, p_kh, p_kl, 1.0f);
    prep_v<<<(B_ * C_ * N_ / 4 + 255) / 256, 256>>>(input);

    attn_mma_kernel<<<B_ * (M_ / 64), 128, ATTN_SMEM>>>();

    epi_kernel<<<B_ * (M_ / 64) * 2, THREADS, epi_smem>>>(weight, gamma, beta, rmean, rvar, out);
}

// round 8
// speedup vs baseline: 2.0477x; 2.0477x over previous
#include <cuda_runtime.h>
#include <cuda_fp16.h>
#include <cstdint>

#define B_    8
#define C_    128
#define N_    4096
#define M_    4096
#define OUT_  128
#define LOG2E 1.4426950408889634f

// single shared-mem declaration for the whole TU (nvcc requires consistency)
extern __shared__ char dyn_smem[];

// ---------------------------------------------------------------------------
// static device scratch (allocation-free)
// ---------------------------------------------------------------------------
__device__ __half g_qh[(size_t)B_ * M_ * C_];   // [b][m][c] normalized*log2e (fp16)
__device__ __half g_kh[(size_t)B_ * N_ * C_];   // [b][n][c] normalized (fp16)
__device__ __half g_vh[(size_t)B_ * C_ * N_];   // [b][c][n] raw fp16
__device__ float  g_agg[(size_t)B_ * M_ * C_];  // [b][m][c]

// ---------------------------------------------------------------------------
// helpers (base-ISA only: ldmatrix / mma.sync / cp.async)
// ---------------------------------------------------------------------------
__device__ __forceinline__ uint32_t smem_u32(const void* p) {
    uint32_t a;
    asm("{ .reg .u64 t; cvta.to.shared.u64 t, %1; cvt.u32.u64 %0, t; }" : "=r"(a) : "l"(p));
    return a;
}
__device__ __forceinline__ void ldsm4(uint32_t* r, uint32_t addr) {
    asm volatile("ldmatrix.sync.aligned.m8n8.x4.shared.b16 {%0,%1,%2,%3}, [%4];"
                 : "=r"(r[0]), "=r"(r[1]), "=r"(r[2]), "=r"(r[3]) : "r"(addr));
}
__device__ __forceinline__ void mma16816(float* d, const uint32_t* a, const uint32_t* b) {
    asm volatile("mma.sync.aligned.m16n8k16.row.col.f32.f16.f16.f32 "
                 "{%0,%1,%2,%3}, {%4,%5,%6,%7}, {%8,%9}, {%0,%1,%2,%3};"
                 : "+f"(d[0]), "+f"(d[1]), "+f"(d[2]), "+f"(d[3])
                 : "r"(a[0]), "r"(a[1]), "r"(a[2]), "r"(a[3]), "r"(b[0]), "r"(b[1]));
}
__device__ __forceinline__ void cpasync16(uint32_t saddr, const void* gaddr) {
    asm volatile("cp.async.cg.shared.global [%0], [%1], 16;" :: "r"(saddr), "l"(gaddr));
}
#define CP_COMMIT() asm volatile("cp.async.commit_group;" ::: "memory")
#define CP_WAIT1()  asm volatile("cp.async.wait_group 1;" ::: "memory")
__device__ __forceinline__ float fast_exp2(float x) {
    float r;
    asm("ex2.approx.ftz.f32 %0, %1;" : "=f"(r) : "f"(x));
    return r;
}
__device__ __forceinline__ uint32_t pack_h2(float lo, float hi) {
    __half2 h = __floats2half2_rn(lo, hi);   // lo -> low 16 bits
    return *(uint32_t*)&h;
}

// ---------------------------------------------------------------------------
// prep: normalize over C, transpose to [b][l][c], fp16
// ---------------------------------------------------------------------------
__global__ __launch_bounds__(256, 1)
void prep_qk(const float* __restrict__ x, __half* __restrict__ hi_out, float extra_scale) {
    float* t  = (float*)dyn_smem;              // [128][129]
    float* rn = t + 128 * 129;
    int blk = blockIdx.x;
    int b = blk >> 5, l0 = (blk & 31) * 128;
    int tid = threadIdx.x;
    const float* src = x + (size_t)b * C_ * 4096 + l0;
    for (int idx = tid; idx < 128 * 128; idx += 256) {
        int c = idx >> 7, l = idx & 127;
        t[c * 129 + l] = src[(size_t)c * 4096 + l];
    }
    __syncthreads();
    if (tid < 128) {
        float s = 0.f;
#pragma unroll 8
        for (int c = 0; c < 128; c++) { float v = t[c * 129 + tid]; s += v * v; }
        rn[tid] = extra_scale / fmaxf(sqrtf(s), 1e-12f);
    }
    __syncthreads();
    for (int idx = tid; idx < 128 * 128; idx += 256) {
        int l = idx >> 7, c = idx & 127;
        float v = t[c * 129 + l] * rn[l];
        hi_out[((size_t)b * 4096 + l0 + l) * C_ + c] = __float2half_rn(v);
    }
}

__global__ void prep_v(const float* __restrict__ x) {
    size_t i = (size_t)blockIdx.x * 256 + threadIdx.x;
    if (i >= (size_t)B_ * C_ * N_ / 4) return;
    float4 v = ((const float4*)x)[i];
    ((uint2*)g_vh)[i] = make_uint2(pack_h2(v.x, v.y), pack_h2(v.z, v.w));
}

// ---------------------------------------------------------------------------
// Pure-fp16 HMMA flash attention.
// grid = B*(M/128)=256, 256 threads (8 warps, 16 m-rows each).
// N-tile 128, double-buffered K/V via cp.async.
// smem: Q 32K | 2 x { K 32K | V 32K } = 160K, 1 CTA/SM
// ---------------------------------------------------------------------------
#define SMQ  0
#define SMKV 32768
#define ATTN_SMEM 163840

__global__ __launch_bounds__(256, 1)
void attn_mma_kernel() {
    char* smc = dyn_smem;
    uint32_t sbase = smem_u32(smc);

    int tid = threadIdx.x;
    int w = tid >> 5, ln = tid & 31;
    int b  = blockIdx.x >> 5;
    int m0 = (blockIdx.x & 31) * 128;

    // ---- load Q tile [128m][128c] (once) ----
    {
        const uint4* qg = (const uint4*)(g_qh + ((size_t)b * M_ + m0) * C_);
        for (int idx = tid; idx < 2048; idx += 256) {
            int row = idx >> 4, ch = idx & 15;
            uint32_t off = row * 256 + ((ch ^ (row & 7)) << 4);
            *(uint4*)(smc + SMQ + off) = qg[row * 16 + ch];
        }
    }

    // tile loader: K [128n][128c] + V [128c][128n], both 256B rows
    auto issue_tiles = [&](int buf, int it) {
        int n0 = it * 128;
        uint32_t kb = sbase + SMKV + buf * 65536;
        const char* kg = (const char*)(g_kh + ((size_t)b * N_ + n0) * C_);
#pragma unroll
        for (int i = 0; i < 8; i++) {
            int idx = tid + i * 256;
            int row = idx >> 4, ch = idx & 15;
            uint32_t off = row * 256 + ((ch ^ (row & 7)) << 4);
            cpasync16(kb + off, kg + row * 256 + ch * 16);
        }
        const char* vg = (const char*)(g_vh + (size_t)b * C_ * N_ + n0);
#pragma unroll
        for (int i = 0; i < 8; i++) {
            int idx = tid + i * 256;
            int row = idx >> 4, ch = idx & 15;
            uint32_t off = row * 256 + ((ch ^ (row & 7)) << 4);
            cpasync16(kb + 32768 + off, vg + (size_t)row * 8192 + ch * 16);
        }
    };

    float oacc[16][4];
#pragma unroll
    for (int i = 0; i < 16; i++)
#pragma unroll
        for (int j = 0; j < 4; j++) oacc[i][j] = 0.f;
    float rs0 = 0.f, rs1 = 0.f;

    issue_tiles(0, 0);
    CP_COMMIT();

    for (int it = 0; it < 32; it++) {
        int buf = it & 1;
        __syncthreads();                       // prev reads of buf^1 done (+Q visible on it=0)
        if (it + 1 < 32) issue_tiles(buf ^ 1, it + 1);
        CP_COMMIT();
        CP_WAIT1();                            // tile `it` landed
        __syncthreads();

        uint32_t kbase = sbase + SMKV + buf * 65536;
        uint32_t vbase = kbase + 32768;

        // ---- S = Q.K^T  [16m x 128n per warp] ----
        float sacc[16][4];
#pragma unroll
        for (int i = 0; i < 16; i++)
#pragma unroll
            for (int j = 0; j < 4; j++) sacc[i][j] = 0.f;

#pragma unroll
        for (int ks = 0; ks < 8; ks++) {
            uint32_t qh[4];
            {
                int r = 16 * w + (ln & 15);
                int ch = 2 * ks + (ln >> 4);
                uint32_t off = r * 256 + ((ch ^ (r & 7)) << 4);
                ldsm4(qh, sbase + SMQ + off);
            }
#pragma unroll
            for (int p = 0; p < 8; p++) {
                uint32_t bh[4];
                int r = 16 * p + ((ln >> 4) << 3) + (ln & 7);
                int ch = 2 * ks + ((ln >> 3) & 1);
                uint32_t off = r * 256 + ((ch ^ (r & 7)) << 4);
                ldsm4(bh, kbase + off);
                mma16816(sacc[2*p],   qh, bh);
                mma16816(sacc[2*p+1], qh, bh + 2);
            }
        }

        // ---- P = exp2(S) (max-free: scores bounded), fp16 pack, rowsum ----
        uint32_t phi[16][2];
#pragma unroll
        for (int nb = 0; nb < 16; nb++) {
            float p0 = fast_exp2(sacc[nb][0]);
            float p1 = fast_exp2(sacc[nb][1]);
            float p2 = fast_exp2(sacc[nb][2]);
            float p3 = fast_exp2(sacc[nb][3]);
            rs0 += p0 + p1;
            rs1 += p2 + p3;
            phi[nb][0] = pack_h2(p0, p1);
            phi[nb][1] = pack_h2(p2, p3);
        }

        // ---- O += P.V^T  [16m x 128c per warp, contract n=128] ----
#pragma unroll
        for (int kn = 0; kn < 8; kn++) {
            uint32_t ah[4] = {phi[2*kn][0], phi[2*kn][1], phi[2*kn+1][0], phi[2*kn+1][1]};
#pragma unroll
            for (int g = 0; g < 2; g++) {
#pragma unroll
                for (int p = 0; p < 4; p++) {
                    uint32_t vh[4];
                    int r = 16 * (4 * g + p) + ((ln >> 4) << 3) + (ln & 7);
                    int ch = 2 * kn + ((ln >> 3) & 1);
                    uint32_t off = r * 256 + ((ch ^ (r & 7)) << 4);
                    ldsm4(vh, vbase + off);
                    int cb = 8 * g + 2 * p;
                    mma16816(oacc[cb],     ah, vh);
                    mma16816(oacc[cb + 1], ah, vh + 2);
                }
            }
        }
    }

    // ---- finalize: divide by row sums, store [b][m][c] ----
    rs0 += __shfl_xor_sync(0xffffffffu, rs0, 1);
    rs0 += __shfl_xor_sync(0xffffffffu, rs0, 2);
    rs1 += __shfl_xor_sync(0xffffffffu, rs1, 1);
    rs1 += __shfl_xor_sync(0xffffffffu, rs1, 2);
    float inv0 = 1.0f / rs0, inv1 = 1.0f / rs1;

    float* dst = g_agg + ((size_t)(b * M_ + m0 + 16 * w + (ln >> 2))) * C_ + 2 * (ln & 3);
#pragma unroll
    for (int cb = 0; cb < 16; cb++) {
        *(float2*)(dst + 8 * cb)          = make_float2(oacc[cb][0] * inv0, oacc[cb][1] * inv0);
        *(float2*)(dst + 8 * C_ + 8 * cb) = make_float2(oacc[cb][2] * inv1, oacc[cb][3] * inv1);
    }
}

// ---------------------------------------------------------------------------
// epilogue: out[b][o][m] = BN(LeakyReLU(agg[b][m][:] . W[:,o]))
// OUT split in halves per CTA for occupancy.
// grid = B*(M/64)*2 = 1024, 256 threads (16x16), microtile 4m x 4o
// ---------------------------------------------------------------------------
#define TM 64
#define A_LD 132
#define OH 64
#define THREADS 256
__global__ __launch_bounds__(THREADS)
void epi_kernel(const float* __restrict__ w,
                const float* __restrict__ gamma,
                const float* __restrict__ beta,
                const float* __restrict__ rmean,
                const float* __restrict__ rvar,
                float* __restrict__ out) {
    float* ws = (float*)dyn_smem;        // [128][64]
    float* as = ws + C_ * OH;            // [64][132]
    float* sc = as + TM * A_LD;          // [64]
    float* bi = sc + OH;                 // [64]

    int bm = blockIdx.x;
    int half = bm & 1;
    int rest = bm >> 1;
    int b  = rest >> 6;
    int m0 = (rest & 63) * TM;
    int o0 = half * OH;
    int tid = threadIdx.x;
    int tx = tid & 15, ty = tid >> 4;

    for (int idx = tid; idx < C_ * (OH / 4); idx += THREADS) {
        int c = idx >> 4, o4 = idx & 15;
        *(float4*)&ws[c * OH + 4 * o4] = *(const float4*)&w[c * OUT_ + o0 + 4 * o4];
    }
    for (int idx = tid; idx < TM * (C_ / 4); idx += THREADS) {
        int m = idx >> 5, c4 = idx & 31;
        float4 v = *(const float4*)&g_agg[((size_t)(b * M_ + m0 + m)) * C_ + 4 * c4];
        *(float4*)&as[m * A_LD + 4 * c4] = v;
    }
    if (tid < OH) {
        int o = o0 + tid;
        float s = rsqrtf(rvar[o] + 1e-5f) * gamma[o];
        sc[tid] = s;
        bi[tid] = beta[o] - rmean[o] * s;
    }
    __syncthreads();

    float acc[4][4];
#pragma unroll
    for (int r = 0; r < 4; r++)
#pragma unroll
        for (int j = 0; j < 4; j++) acc[r][j] = 0.f;

    for (int c = 0; c < C_; c += 4) {
        float areg[4][4];
#pragma unroll
        for (int r = 0; r < 4; r++) {
            float4 t = *(const float4*)&as[(4 * ty + r) * A_LD + c];
            areg[r][0] = t.x; areg[r][1] = t.y; areg[r][2] = t.z; areg[r][3] = t.w;
        }
#pragma unroll
        for (int cc = 0; cc < 4; cc++) {
            float4 wv = *(const float4*)&ws[(c + cc) * OH + 4 * tx];
            float wa[4] = {wv.x, wv.y, wv.z, wv.w};
#pragma unroll
            for (int r = 0; r < 4; r++)
#pragma unroll
                for (int j = 0; j < 4; j++)
                    acc[r][j] += areg[r][cc] * wa[j];
        }
    }
#pragma unroll
    for (int r = 0; r < 4; r++) {
        int m = m0 + 4 * ty + r;
#pragma unroll
        for (int j = 0; j < 4; j++) {
            int ol = 4 * tx + j;
            float z = acc[r][j];
            z = (z >= 0.f) ? z : 0.01f * z;
            out[((size_t)b * OUT_ + o0 + ol) * M_ + m] = z * sc[ol] + bi[ol];
        }
    }
}

// ---------------------------------------------------------------------------
extern "C" void kernel_launch(void* const* d_in, const int* in_sizes, int n_in,
                              void* d_out, int out_size) {
    const float* input  = (const float*)d_in[0];
    const float* tg     = (const float*)d_in[1];
    const float* weight = (const float*)d_in[2];
    const float* gamma  = (const float*)d_in[3];
    const float* beta   = (const float*)d_in[4];
    const float* rmean  = (const float*)d_in[5];
    const float* rvar   = (const float*)d_in[6];
    float* out = (float*)d_out;

    __half *p_qh, *p_kh;
    cudaGetSymbolAddress((void**)&p_qh, g_qh);
    cudaGetSymbolAddress((void**)&p_kh, g_kh);

    const int prep_smem = (128 * 129 + 128) * (int)sizeof(float);
    const int epi_smem  = (C_ * OH + TM * A_LD + 2 * OH) * (int)sizeof(float);
    cudaFuncSetAttribute(prep_qk, cudaFuncAttributeMaxDynamicSharedMemorySize, prep_smem);
    cudaFuncSetAttribute(attn_mma_kernel, cudaFuncAttributeMaxDynamicSharedMemorySize, ATTN_SMEM);
    cudaFuncSetAttribute(epi_kernel, cudaFuncAttributeMaxDynamicSharedMemorySize, epi_smem);

    prep_qk<<<B_ * (M_ / 128), 256, prep_smem>>>(tg,    p_qh, LOG2E);
    prep_qk<<<B_ * (N_ / 128), 256, prep_smem>>>(input, p_kh, 1.0f);
    prep_v<<<(B_ * C_ * N_ / 4 + 255) / 256, 256>>>(input);

    attn_mma_kernel<<<B_ * (M_ / 128), 256, ATTN_SMEM>>>();

    epi_kernel<<<B_ * (M_ / 64) * 2, THREADS, epi_smem>>>(weight, gamma, beta, rmean, rvar, out);
}

// round 13
// speedup vs baseline: 2.3827x; 1.1636x over previous
#include <cuda_runtime.h>
#include <cuda_fp16.h>
#include <cstdint>

#define B_    8
#define C_    128
#define N_    4096
#define M_    4096
#define OUT_  128
#define LOG2E 1.4426950408889634f

// single shared-mem declaration for the whole TU (nvcc requires consistency)
extern __shared__ char dyn_smem[];

// ---------------------------------------------------------------------------
// static device scratch (allocation-free)
// ---------------------------------------------------------------------------
__device__ __half g_qh[(size_t)B_ * M_ * C_];   // [b][m][c] normalized*log2e (fp16)
__device__ __half g_kh[(size_t)B_ * N_ * C_];   // [b][n][c] normalized (fp16)
__device__ __half g_vh[(size_t)B_ * C_ * N_];   // [b][c][n] raw fp16
__device__ __half g_wh[C_ * OUT_];              // [o][c] weight hi (TRANSPOSED for MMA B-operand)
__device__ __half g_wl[C_ * OUT_];              // [o][c] weight residual
__device__ float  g_sc[OUT_];                   // BN scale
__device__ float  g_bi[OUT_];                   // BN bias

// ---------------------------------------------------------------------------
// helpers (base-ISA only: ldmatrix / mma.sync / cp.async)
// ---------------------------------------------------------------------------
__device__ __forceinline__ uint32_t smem_u32(const void* p) {
    uint32_t a;
    asm("{ .reg .u64 t; cvta.to.shared.u64 t, %1; cvt.u32.u64 %0, t; }" : "=r"(a) : "l"(p));
    return a;
}
__device__ __forceinline__ void ldsm4(uint32_t* r, uint32_t addr) {
    asm volatile("ldmatrix.sync.aligned.m8n8.x4.shared.b16 {%0,%1,%2,%3}, [%4];"
                 : "=r"(r[0]), "=r"(r[1]), "=r"(r[2]), "=r"(r[3]) : "r"(addr));
}
__device__ __forceinline__ void mma16816(float* d, const uint32_t* a, const uint32_t* b) {
    asm volatile("mma.sync.aligned.m16n8k16.row.col.f32.f16.f16.f32 "
                 "{%0,%1,%2,%3}, {%4,%5,%6,%7}, {%8,%9}, {%0,%1,%2,%3};"
                 : "+f"(d[0]), "+f"(d[1]), "+f"(d[2]), "+f"(d[3])
                 : "r"(a[0]), "r"(a[1]), "r"(a[2]), "r"(a[3]), "r"(b[0]), "r"(b[1]));
}
__device__ __forceinline__ void cpasync16(uint32_t saddr, const void* gaddr) {
    asm volatile("cp.async.cg.shared.global [%0], [%1], 16;" :: "r"(saddr), "l"(gaddr));
}
#define CP_COMMIT() asm volatile("cp.async.commit_group;" ::: "memory")
#define CP_WAIT1()  asm volatile("cp.async.wait_group 1;" ::: "memory")
__device__ __forceinline__ float fast_exp2(float x) {
    float r;
    asm("ex2.approx.ftz.f32 %0, %1;" : "=f"(r) : "f"(x));
    return r;
}
__device__ __forceinline__ uint32_t pack_h2(float lo, float hi) {
    __half2 h = __floats2half2_rn(lo, hi);   // lo -> low 16 bits
    return *(uint32_t*)&h;
}

// ---------------------------------------------------------------------------
// prep: normalize over C, transpose to [b][l][c], fp16
// ---------------------------------------------------------------------------
__global__ __launch_bounds__(256, 1)
void prep_qk(const float* __restrict__ x, __half* __restrict__ hi_out, float extra_scale) {
    float* t  = (float*)dyn_smem;              // [128][129]
    float* rn = t + 128 * 129;
    int blk = blockIdx.x;
    int b = blk >> 5, l0 = (blk & 31) * 128;
    int tid = threadIdx.x;
    const float* src = x + (size_t)b * C_ * 4096 + l0;
    for (int idx = tid; idx < 128 * 128; idx += 256) {
        int c = idx >> 7, l = idx & 127;
        t[c * 129 + l] = src[(size_t)c * 4096 + l];
    }
    __syncthreads();
    if (tid < 128) {
        float s = 0.f;
#pragma unroll 8
        for (int c = 0; c < 128; c++) { float v = t[c * 129 + tid]; s += v * v; }
        rn[tid] = extra_scale / fmaxf(sqrtf(s), 1e-12f);
    }
    __syncthreads();
    for (int idx = tid; idx < 128 * 128; idx += 256) {
        int l = idx >> 7, c = idx & 127;
        float v = t[c * 129 + l] * rn[l];
        hi_out[((size_t)b * 4096 + l0 + l) * C_ + c] = __float2half_rn(v);
    }
}

__global__ void prep_v(const float* __restrict__ x) {
    size_t i = (size_t)blockIdx.x * 256 + threadIdx.x;
    if (i >= (size_t)B_ * C_ * N_ / 4) return;
    float4 v = ((const float4*)x)[i];
    ((uint2*)g_vh)[i] = make_uint2(pack_h2(v.x, v.y), pack_h2(v.z, v.w));
}

// W hi/lo split (TRANSPOSED to [o][c]) + BN constants
__global__ void prep_w(const float* __restrict__ w, const float* __restrict__ gamma,
                       const float* __restrict__ beta, const float* __restrict__ rmean,
                       const float* __restrict__ rvar) {
    int i = blockIdx.x * 256 + threadIdx.x;
    if (i < C_ * OUT_) {
        int c = i / OUT_, o = i % OUT_;   // w is [c][o]; read coalesced
        float v = w[i];
        __half h = __float2half_rn(v);
        g_wh[o * C_ + c] = h;                                   // store [o][c]
        g_wl[o * C_ + c] = __float2half_rn(v - __half2float(h));
    }
    if (i < OUT_) {
        float s = rsqrtf(rvar[i] + 1e-5f) * gamma[i];
        g_sc[i] = s;
        g_bi[i] = beta[i] - rmean[i] * s;
    }
}

// ---------------------------------------------------------------------------
// Pure-fp16 HMMA flash attention + fused projection/LeakyReLU/BN epilogue.
// grid = B*(M/128)=256, 256 threads (8 warps, 16 m-rows each).
// N-tile 128, double-buffered K/V via cp.async.
// smem: Q 32K | 2 x { K 32K | V 32K } | Whi 32K | Wlo 32K = 224K, 1 CTA/SM
// ---------------------------------------------------------------------------
#define SMQ  0
#define SMKV 32768
#define SMWH 163840
#define SMWL 196608
#define ATTN_SMEM 229376

__global__ __launch_bounds__(256, 1)
void attn_mma_kernel(float* __restrict__ out) {
    char* smc = dyn_smem;
    uint32_t sbase = smem_u32(smc);

    int tid = threadIdx.x;
    int w = tid >> 5, ln = tid & 31;
    int b  = blockIdx.x >> 5;
    int m0 = (blockIdx.x & 31) * 128;

    // ---- load Q tile [128m][128c] and W hi/lo [128o][128c] (once) ----
    {
        const uint4* qg = (const uint4*)(g_qh + ((size_t)b * M_ + m0) * C_);
        const uint4* whg = (const uint4*)g_wh;
        const uint4* wlg = (const uint4*)g_wl;
        for (int idx = tid; idx < 2048; idx += 256) {
            int row = idx >> 4, ch = idx & 15;
            uint32_t off = row * 256 + ((ch ^ (row & 7)) << 4);
            *(uint4*)(smc + SMQ + off)  = qg[row * 16 + ch];
            *(uint4*)(smc + SMWH + off) = whg[row * 16 + ch];
            *(uint4*)(smc + SMWL + off) = wlg[row * 16 + ch];
        }
    }

    // tile loader: K [128n][128c] + V [128c][128n], both 256B rows
    auto issue_tiles = [&](int buf, int it) {
        int n0 = it * 128;
        uint32_t kb = sbase + SMKV + buf * 65536;
        const char* kg = (const char*)(g_kh + ((size_t)b * N_ + n0) * C_);
#pragma unroll
        for (int i = 0; i < 8; i++) {
            int idx = tid + i * 256;
            int row = idx >> 4, ch = idx & 15;
            uint32_t off = row * 256 + ((ch ^ (row & 7)) << 4);
            cpasync16(kb + off, kg + row * 256 + ch * 16);
        }
        const char* vg = (const char*)(g_vh + (size_t)b * C_ * N_ + n0);
#pragma unroll
        for (int i = 0; i < 8; i++) {
            int idx = tid + i * 256;
            int row = idx >> 4, ch = idx & 15;
            uint32_t off = row * 256 + ((ch ^ (row & 7)) << 4);
            cpasync16(kb + 32768 + off, vg + (size_t)row * 8192 + ch * 16);
        }
    };

    float oacc[16][4];
#pragma unroll
    for (int i = 0; i < 16; i++)
#pragma unroll
        for (int j = 0; j < 4; j++) oacc[i][j] = 0.f;
    float rs0 = 0.f, rs1 = 0.f;

    issue_tiles(0, 0);
    CP_COMMIT();

    for (int it = 0; it < 32; it++) {
        int buf = it & 1;
        __syncthreads();                       // prev reads of buf^1 done (+Q/W visible on it=0)
        if (it + 1 < 32) issue_tiles(buf ^ 1, it + 1);
        CP_COMMIT();
        CP_WAIT1();                            // tile `it` landed
        __syncthreads();

        uint32_t kbase = sbase + SMKV + buf * 65536;
        uint32_t vbase = kbase + 32768;

        // ---- S = Q.K^T  [16m x 128n per warp] ----
        float sacc[16][4];
#pragma unroll
        for (int i = 0; i < 16; i++)
#pragma unroll
            for (int j = 0; j < 4; j++) sacc[i][j] = 0.f;

#pragma unroll
        for (int ks = 0; ks < 8; ks++) {
            uint32_t qh[4];
            {
                int r = 16 * w + (ln & 15);
                int ch = 2 * ks + (ln >> 4);
                uint32_t off = r * 256 + ((ch ^ (r & 7)) << 4);
                ldsm4(qh, sbase + SMQ + off);
            }
#pragma unroll
            for (int p = 0; p < 8; p++) {
                uint32_t bh[4];
                int r = 16 * p + ((ln >> 4) << 3) + (ln & 7);
                int ch = 2 * ks + ((ln >> 3) & 1);
                uint32_t off = r * 256 + ((ch ^ (r & 7)) << 4);
                ldsm4(bh, kbase + off);
                mma16816(sacc[2*p],   qh, bh);
                mma16816(sacc[2*p+1], qh, bh + 2);
            }
        }

        // ---- P = exp2(S) (max-free: scores bounded), fp16 pack, rowsum ----
        uint32_t phi[16][2];
#pragma unroll
        for (int nb = 0; nb < 16; nb++) {
            float p0 = fast_exp2(sacc[nb][0]);
            float p1 = fast_exp2(sacc[nb][1]);
            float p2 = fast_exp2(sacc[nb][2]);
            float p3 = fast_exp2(sacc[nb][3]);
            rs0 += p0 + p1;
            rs1 += p2 + p3;
            phi[nb][0] = pack_h2(p0, p1);
            phi[nb][1] = pack_h2(p2, p3);
        }

        // ---- O += P.V^T  [16m x 128c per warp, contract n=128] ----
#pragma unroll
        for (int kn = 0; kn < 8; kn++) {
            uint32_t ah[4] = {phi[2*kn][0], phi[2*kn][1], phi[2*kn+1][0], phi[2*kn+1][1]};
#pragma unroll
            for (int g = 0; g < 2; g++) {
#pragma unroll
                for (int p = 0; p < 4; p++) {
                    uint32_t vh[4];
                    int r = 16 * (4 * g + p) + ((ln >> 4) << 3) + (ln & 7);
                    int ch = 2 * kn + ((ln >> 3) & 1);
                    uint32_t off = r * 256 + ((ch ^ (r & 7)) << 4);
                    ldsm4(vh, vbase + off);
                    int cb = 8 * g + 2 * p;
                    mma16816(oacc[cb],     ah, vh);
                    mma16816(oacc[cb + 1], ah, vh + 2);
                }
            }
        }
    }

    // =================== fused epilogue ===================
    // row sums -> O/l in fp16 hi/lo; project with W hi/lo (3-product);
    // LeakyReLU + BN; stage [o][m] in smem; coalesced write out[b][o][m].
    rs0 += __shfl_xor_sync(0xffffffffu, rs0, 1);
    rs0 += __shfl_xor_sync(0xffffffffu, rs0, 2);
    rs1 += __shfl_xor_sync(0xffffffffu, rs1, 1);
    rs1 += __shfl_xor_sync(0xffffffffu, rs1, 2);
    float inv0 = 1.0f / rs0, inv1 = 1.0f / rs1;

    // pack O/l hi + residual lo (same frag layout as mainloop P)
    uint32_t ohi[16][2], olo[16][2];
#pragma unroll
    for (int nb = 0; nb < 16; nb++) {
        float e0 = oacc[nb][0] * inv0;
        float e1 = oacc[nb][1] * inv0;
        float e2 = oacc[nb][2] * inv1;
        float e3 = oacc[nb][3] * inv1;
        __half h0 = __float2half_rn(e0), h1 = __float2half_rn(e1);
        __half h2 = __float2half_rn(e2), h3 = __float2half_rn(e3);
        ohi[nb][0] = (uint32_t)*(unsigned short*)&h0 | ((uint32_t)*(unsigned short*)&h1 << 16);
        ohi[nb][1] = (uint32_t)*(unsigned short*)&h2 | ((uint32_t)*(unsigned short*)&h3 << 16);
        olo[nb][0] = pack_h2(e0 - __half2float(h0), e1 - __half2float(h1));
        olo[nb][1] = pack_h2(e2 - __half2float(h2), e3 - __half2float(h3));
    }

    // epi MMA: z[16m][128o] = (O/l) . W   (W tile is [o][c] => B rows = o, cols = c)
    float eacc[16][4];
#pragma unroll
    for (int i = 0; i < 16; i++)
#pragma unroll
        for (int j = 0; j < 4; j++) eacc[i][j] = 0.f;

#pragma unroll
    for (int kc = 0; kc < 8; kc++) {
        uint32_t ah[4] = {ohi[2*kc][0], ohi[2*kc][1], ohi[2*kc+1][0], ohi[2*kc+1][1]};
        uint32_t al[4] = {olo[2*kc][0], olo[2*kc][1], olo[2*kc+1][0], olo[2*kc+1][1]};
#pragma unroll
        for (int p = 0; p < 8; p++) {
            int r = 16 * p + ((ln >> 4) << 3) + (ln & 7);
            int ch = 2 * kc + ((ln >> 3) & 1);
            uint32_t off = r * 256 + ((ch ^ (r & 7)) << 4);
            uint32_t wh[4], wl[4];
            ldsm4(wh, sbase + SMWH + off);
            ldsm4(wl, sbase + SMWL + off);
            mma16816(eacc[2*p],   ah, wh);
            mma16816(eacc[2*p+1], ah, wh + 2);
            mma16816(eacc[2*p],   ah, wl);
            mma16816(eacc[2*p+1], ah, wl + 2);
            mma16816(eacc[2*p],   al, wh);
            mma16816(eacc[2*p+1], al, wh + 2);
        }
    }

    // LeakyReLU + BN, scatter to stage [128o][132m] (reuses KV smem)
    __syncthreads();            // all warps done with last V tile before overwrite
    float* stage = (float*)(smc + SMKV);
    int r0 = 16 * w + (ln >> 2);
    int r1 = r0 + 8;
#pragma unroll
    for (int cb = 0; cb < 16; cb++) {
        int o0c = 8 * cb + 2 * (ln & 3);
        float s0 = g_sc[o0c],     b0 = g_bi[o0c];
        float s1 = g_sc[o0c + 1], b1 = g_bi[o0c + 1];
        float z0 = eacc[cb][0]; z0 = (z0 >= 0.f) ? z0 : 0.01f * z0;
        float z1 = eacc[cb][1]; z1 = (z1 >= 0.f) ? z1 : 0.01f * z1;
        float z2 = eacc[cb][2]; z2 = (z2 >= 0.f) ? z2 : 0.01f * z2;
        float z3 = eacc[cb][3]; z3 = (z3 >= 0.f) ? z3 : 0.01f * z3;
        stage[o0c * 132 + r0]       = z0 * s0 + b0;
        stage[(o0c + 1) * 132 + r0] = z1 * s1 + b1;
        stage[o0c * 132 + r1]       = z2 * s0 + b0;
        stage[(o0c + 1) * 132 + r1] = z3 * s1 + b1;
    }
    __syncthreads();

    // coalesced write: out[b][o][m0 + m]
    float* dst = out + ((size_t)b * OUT_) * M_ + m0;
    for (int idx = tid; idx < 128 * 32; idx += 256) {
        int o = idx >> 5, m4 = idx & 31;
        *(float4*)(dst + (size_t)o * M_ + 4 * m4) = *(float4*)(stage + o * 132 + 4 * m4);
    }
}

// ---------------------------------------------------------------------------
extern "C" void kernel_launch(void* const* d_in, const int* in_sizes, int n_in,
                              void* d_out, int out_size) {
    const float* input  = (const float*)d_in[0];
    const float* tg     = (const float*)d_in[1];
    const float* weight = (const float*)d_in[2];
    const float* gamma  = (const float*)d_in[3];
    const float* beta   = (const float*)d_in[4];
    const float* rmean  = (const float*)d_in[5];
    const float* rvar   = (const float*)d_in[6];
    float* out = (float*)d_out;

    __half *p_qh, *p_kh;
    cudaGetSymbolAddress((void**)&p_qh, g_qh);
    cudaGetSymbolAddress((void**)&p_kh, g_kh);

    const int prep_smem = (128 * 129 + 128) * (int)sizeof(float);
    cudaFuncSetAttribute(prep_qk, cudaFuncAttributeMaxDynamicSharedMemorySize, prep_smem);
    cudaFuncSetAttribute(attn_mma_kernel, cudaFuncAttributeMaxDynamicSharedMemorySize, ATTN_SMEM);

    prep_qk<<<B_ * (M_ / 128), 256, prep_smem>>>(tg,    p_qh, LOG2E);
    prep_qk<<<B_ * (N_ / 128), 256, prep_smem>>>(input, p_kh, 1.0f);
    prep_v<<<(B_ * C_ * N_ / 4 + 255) / 256, 256>>>(input);
    prep_w<<<(C_ * OUT_ + 255) / 256, 256>>>(weight, gamma, beta, rmean, rvar);

    attn_mma_kernel<<<B_ * (M_ / 128), 256, ATTN_SMEM>>>(out);
}

// round 14
// speedup vs baseline: 2.4880x; 1.0442x over previous
#include <cuda_runtime.h>
#include <cuda_fp16.h>
#include <cstdint>

#define B_    8
#define C_    128
#define N_    4096
#define M_    4096
#define OUT_  128
#define LOG2E 1.4426950408889634f

// single shared-mem declaration for the whole TU (nvcc requires consistency)
extern __shared__ char dyn_smem[];

// ---------------------------------------------------------------------------
// static device scratch (allocation-free)
// ---------------------------------------------------------------------------
__device__ __half g_qh[(size_t)B_ * M_ * C_];   // [b][m][c] normalized*log2e (fp16)
__device__ __half g_kh[(size_t)B_ * N_ * C_];   // [b][n][c] normalized (fp16)
__device__ __half g_vh[(size_t)B_ * C_ * N_];   // [b][c][n] raw fp16
__device__ __half g_wh[C_ * OUT_];              // [o][c] weight hi (transposed for MMA B)
__device__ __half g_wl[C_ * OUT_];              // [o][c] weight residual
__device__ float  g_sc[OUT_];                   // BN scale
__device__ float  g_bi[OUT_];                   // BN bias

// ---------------------------------------------------------------------------
// helpers (base-ISA only: ldmatrix / mma.sync / cp.async)
// ---------------------------------------------------------------------------
__device__ __forceinline__ uint32_t smem_u32(const void* p) {
    uint32_t a;
    asm("{ .reg .u64 t; cvta.to.shared.u64 t, %1; cvt.u32.u64 %0, t; }" : "=r"(a) : "l"(p));
    return a;
}
__device__ __forceinline__ void ldsm4(uint32_t* r, uint32_t addr) {
    asm volatile("ldmatrix.sync.aligned.m8n8.x4.shared.b16 {%0,%1,%2,%3}, [%4];"
                 : "=r"(r[0]), "=r"(r[1]), "=r"(r[2]), "=r"(r[3]) : "r"(addr));
}
__device__ __forceinline__ void mma16816(float* d, const uint32_t* a, const uint32_t* b) {
    asm volatile("mma.sync.aligned.m16n8k16.row.col.f32.f16.f16.f32 "
                 "{%0,%1,%2,%3}, {%4,%5,%6,%7}, {%8,%9}, {%0,%1,%2,%3};"
                 : "+f"(d[0]), "+f"(d[1]), "+f"(d[2]), "+f"(d[3])
                 : "r"(a[0]), "r"(a[1]), "r"(a[2]), "r"(a[3]), "r"(b[0]), "r"(b[1]));
}
__device__ __forceinline__ void cpasync16(uint32_t saddr, const void* gaddr) {
    asm volatile("cp.async.cg.shared.global [%0], [%1], 16;" :: "r"(saddr), "l"(gaddr));
}
#define CP_COMMIT() asm volatile("cp.async.commit_group;" ::: "memory")
#define CP_WAIT1()  asm volatile("cp.async.wait_group 1;" ::: "memory")
__device__ __forceinline__ uint32_t pack_h2(float lo, float hi) {
    __half2 h = __floats2half2_rn(lo, hi);   // lo -> low 16 bits
    return *(uint32_t*)&h;
}
__device__ __forceinline__ uint32_t ex2_h2(uint32_t x) {
    uint32_t r;
    asm("ex2.approx.f16x2 %0, %1;" : "=r"(r) : "r"(x));
    return r;
}
__device__ __forceinline__ uint32_t hadd2_(uint32_t a, uint32_t b) {
    uint32_t r;
    asm("add.f16x2 %0, %1, %2;" : "=r"(r) : "r"(a), "r"(b));
    return r;
}
__device__ __forceinline__ float2 h2_to_f2(uint32_t a) {
    __half2 h = *(__half2*)&a;
    return __half22float2(h);
}

// ---------------------------------------------------------------------------
// merged prep kernel (block-range dispatch):
//  blocks [0,256):      tg -> g_qh (normalize over C, transpose, *LOG2E, fp16)
//  blocks [256,512):    input -> g_kh (normalize, transpose, fp16)
//  blocks [512,1536):   input -> g_vh (fp16 convert, layout preserved)
//  blocks [1536,1600):  weight -> g_wh/g_wl ([o][c] hi/lo) + BN constants
// ---------------------------------------------------------------------------
__global__ __launch_bounds__(256, 1)
void prep_all(const float* __restrict__ input, const float* __restrict__ tg,
              const float* __restrict__ w, const float* __restrict__ gamma,
              const float* __restrict__ beta, const float* __restrict__ rmean,
              const float* __restrict__ rvar) {
    int blk = blockIdx.x;
    int tid = threadIdx.x;

    if (blk < 512) {
        const float* x;
        __half* dst;
        float esc;
        int lb;
        if (blk < 256) { x = tg;    dst = g_qh; esc = LOG2E; lb = blk; }
        else           { x = input; dst = g_kh; esc = 1.0f;  lb = blk - 256; }
        float* t  = (float*)dyn_smem;              // [128][129]
        float* rn = t + 128 * 129;
        int b = lb >> 5, l0 = (lb & 31) * 128;
        const float* src = x + (size_t)b * C_ * 4096 + l0;
        for (int idx = tid; idx < 128 * 128; idx += 256) {
            int c = idx >> 7, l = idx & 127;
            t[c * 129 + l] = src[(size_t)c * 4096 + l];
        }
        __syncthreads();
        if (tid < 128) {
            float s = 0.f;
#pragma unroll 8
            for (int c = 0; c < 128; c++) { float v = t[c * 129 + tid]; s += v * v; }
            rn[tid] = esc / fmaxf(sqrtf(s), 1e-12f);
        }
        __syncthreads();
        for (int idx = tid; idx < 128 * 128; idx += 256) {
            int l = idx >> 7, c = idx & 127;
            float v = t[c * 129 + l] * rn[l];
            dst[((size_t)b * 4096 + l0 + l) * C_ + c] = __float2half_rn(v);
        }
    } else if (blk < 1536) {
        // V convert: 1,048,576 uint2 elements over 1024 blocks x 256 threads
        size_t i = (size_t)(blk - 512) * 256 + tid;
        for (; i < (size_t)B_ * C_ * N_ / 4; i += 1024 * 256) {
            float4 v = ((const float4*)input)[i];
            ((uint2*)g_vh)[i] = make_uint2(pack_h2(v.x, v.y), pack_h2(v.z, v.w));
        }
    } else {
        int i = (blk - 1536) * 256 + tid;       // 0 .. 16383
        if (i < C_ * OUT_) {
            int c = i / OUT_, o = i % OUT_;     // w is [c][o]; read coalesced
            float v = w[i];
            __half h = __float2half_rn(v);
            g_wh[o * C_ + c] = h;               // store [o][c]
            g_wl[o * C_ + c] = __float2half_rn(v - __half2float(h));
        }
        if (i < OUT_) {
            float s = rsqrtf(rvar[i] + 1e-5f) * gamma[i];
            g_sc[i] = s;
            g_bi[i] = beta[i] - rmean[i] * s;
        }
    }
}

// ---------------------------------------------------------------------------
// Pure-fp16 HMMA flash attention + fused projection/LeakyReLU/BN epilogue.
// grid = B*(M/128)=256, 256 threads (8 warps, 16 m-rows each).
// N-tile 128, double-buffered K/V via cp.async.
// smem: Q 32K | 2 x { K 32K | V 32K } | Whi 32K | Wlo 32K = 224K, 1 CTA/SM
// ---------------------------------------------------------------------------
#define SMQ  0
#define SMKV 32768
#define SMWH 163840
#define SMWL 196608
#define ATTN_SMEM 229376

__global__ __launch_bounds__(256, 1)
void attn_mma_kernel(float* __restrict__ out) {
    char* smc = dyn_smem;
    uint32_t sbase = smem_u32(smc);

    int tid = threadIdx.x;
    int w = tid >> 5, ln = tid & 31;
    int b  = blockIdx.x >> 5;
    int m0 = (blockIdx.x & 31) * 128;

    // ---- load Q tile [128m][128c] and W hi/lo [128o][128c] (once) ----
    {
        const uint4* qg = (const uint4*)(g_qh + ((size_t)b * M_ + m0) * C_);
        const uint4* whg = (const uint4*)g_wh;
        const uint4* wlg = (const uint4*)g_wl;
        for (int idx = tid; idx < 2048; idx += 256) {
            int row = idx >> 4, ch = idx & 15;
            uint32_t off = row * 256 + ((ch ^ (row & 7)) << 4);
            *(uint4*)(smc + SMQ + off)  = qg[row * 16 + ch];
            *(uint4*)(smc + SMWH + off) = whg[row * 16 + ch];
            *(uint4*)(smc + SMWL + off) = wlg[row * 16 + ch];
        }
    }

    // tile loader: K [128n][128c] + V [128c][128n], both 256B rows
    auto issue_tiles = [&](int buf, int it) {
        int n0 = it * 128;
        uint32_t kb = sbase + SMKV + buf * 65536;
        const char* kg = (const char*)(g_kh + ((size_t)b * N_ + n0) * C_);
#pragma unroll
        for (int i = 0; i < 8; i++) {
            int idx = tid + i * 256;
            int row = idx >> 4, ch = idx & 15;
            uint32_t off = row * 256 + ((ch ^ (row & 7)) << 4);
            cpasync16(kb + off, kg + row * 256 + ch * 16);
        }
        const char* vg = (const char*)(g_vh + (size_t)b * C_ * N_ + n0);
#pragma unroll
        for (int i = 0; i < 8; i++) {
            int idx = tid + i * 256;
            int row = idx >> 4, ch = idx & 15;
            uint32_t off = row * 256 + ((ch ^ (row & 7)) << 4);
            cpasync16(kb + 32768 + off, vg + (size_t)row * 8192 + ch * 16);
        }
    };

    float oacc[16][4];
#pragma unroll
    for (int i = 0; i < 16; i++)
#pragma unroll
        for (int j = 0; j < 4; j++) oacc[i][j] = 0.f;
    float rs0 = 0.f, rs1 = 0.f;

    issue_tiles(0, 0);
    CP_COMMIT();

    for (int it = 0; it < 32; it++) {
        int buf = it & 1;
        __syncthreads();                       // prev reads of buf^1 done (+Q/W visible on it=0)
        if (it + 1 < 32) issue_tiles(buf ^ 1, it + 1);
        CP_COMMIT();
        CP_WAIT1();                            // tile `it` landed
        __syncthreads();

        uint32_t kbase = sbase + SMKV + buf * 65536;
        uint32_t vbase = kbase + 32768;

        // ---- S = Q.K^T  [16m x 128n per warp] ----
        float sacc[16][4];
#pragma unroll
        for (int i = 0; i < 16; i++)
#pragma unroll
            for (int j = 0; j < 4; j++) sacc[i][j] = 0.f;

#pragma unroll
        for (int ks = 0; ks < 8; ks++) {
            uint32_t qh[4];
            {
                int r = 16 * w + (ln & 15);
                int ch = 2 * ks + (ln >> 4);
                uint32_t off = r * 256 + ((ch ^ (r & 7)) << 4);
                ldsm4(qh, sbase + SMQ + off);
            }
#pragma unroll
            for (int p = 0; p < 8; p++) {
                uint32_t bh[4];
                int r = 16 * p + ((ln >> 4) << 3) + (ln & 7);
                int ch = 2 * ks + ((ln >> 3) & 1);
                uint32_t off = r * 256 + ((ch ^ (r & 7)) << 4);
                ldsm4(bh, kbase + off);
                mma16816(sacc[2*p],   qh, bh);
                mma16816(sacc[2*p+1], qh, bh + 2);
            }
        }

        // ---- P = exp2(S) via f16x2 MUFU (max-free: scores bounded, fp16-safe) ----
        uint32_t phi[16][2];
#pragma unroll
        for (int nb = 0; nb < 16; nb++) {
            phi[nb][0] = ex2_h2(pack_h2(sacc[nb][0], sacc[nb][1]));
            phi[nb][1] = ex2_h2(pack_h2(sacc[nb][2], sacc[nb][3]));
        }
        // row sums: 2-level fp16 tree (4-sums), then fp32 accumulate
#pragma unroll
        for (int g = 0; g < 4; g++) {
            uint32_t a0 = hadd2_(hadd2_(phi[4*g][0], phi[4*g+1][0]),
                                 hadd2_(phi[4*g+2][0], phi[4*g+3][0]));
            float2 f0 = h2_to_f2(a0);
            rs0 += f0.x + f0.y;
            uint32_t a1 = hadd2_(hadd2_(phi[4*g][1], phi[4*g+1][1]),
                                 hadd2_(phi[4*g+2][1], phi[4*g+3][1]));
            float2 f1 = h2_to_f2(a1);
            rs1 += f1.x + f1.y;
        }

        // ---- O += P.V^T  [16m x 128c per warp, contract n=128] ----
#pragma unroll
        for (int kn = 0; kn < 8; kn++) {
            uint32_t ah[4] = {phi[2*kn][0], phi[2*kn][1], phi[2*kn+1][0], phi[2*kn+1][1]};
#pragma unroll
            for (int g = 0; g < 2; g++) {
#pragma unroll
                for (int p = 0; p < 4; p++) {
                    uint32_t vh[4];
                    int r = 16 * (4 * g + p) + ((ln >> 4) << 3) + (ln & 7);
                    int ch = 2 * kn + ((ln >> 3) & 1);
                    uint32_t off = r * 256 + ((ch ^ (r & 7)) << 4);
                    ldsm4(vh, vbase + off);
                    int cb = 8 * g + 2 * p;
                    mma16816(oacc[cb],     ah, vh);
                    mma16816(oacc[cb + 1], ah, vh + 2);
                }
            }
        }
    }

    // =================== fused epilogue ===================
    rs0 += __shfl_xor_sync(0xffffffffu, rs0, 1);
    rs0 += __shfl_xor_sync(0xffffffffu, rs0, 2);
    rs1 += __shfl_xor_sync(0xffffffffu, rs1, 1);
    rs1 += __shfl_xor_sync(0xffffffffu, rs1, 2);
    float inv0 = 1.0f / rs0, inv1 = 1.0f / rs1;

    // pack O/l hi + residual lo (same frag layout as mainloop P)
    uint32_t ohi[16][2], olo[16][2];
#pragma unroll
    for (int nb = 0; nb < 16; nb++) {
        float e0 = oacc[nb][0] * inv0;
        float e1 = oacc[nb][1] * inv0;
        float e2 = oacc[nb][2] * inv1;
        float e3 = oacc[nb][3] * inv1;
        __half h0 = __float2half_rn(e0), h1 = __float2half_rn(e1);
        __half h2 = __float2half_rn(e2), h3 = __float2half_rn(e3);
        ohi[nb][0] = (uint32_t)*(unsigned short*)&h0 | ((uint32_t)*(unsigned short*)&h1 << 16);
        ohi[nb][1] = (uint32_t)*(unsigned short*)&h2 | ((uint32_t)*(unsigned short*)&h3 << 16);
        olo[nb][0] = pack_h2(e0 - __half2float(h0), e1 - __half2float(h1));
        olo[nb][1] = pack_h2(e2 - __half2float(h2), e3 - __half2float(h3));
    }

    // epi MMA: z[16m][128o] = (O/l) . W   (W tile is [o][c]: B rows = o, cols = c)
    float eacc[16][4];
#pragma unroll
    for (int i = 0; i < 16; i++)
#pragma unroll
        for (int j = 0; j < 4; j++) eacc[i][j] = 0.f;

#pragma unroll
    for (int kc = 0; kc < 8; kc++) {
        uint32_t ah[4] = {ohi[2*kc][0], ohi[2*kc][1], ohi[2*kc+1][0], ohi[2*kc+1][1]};
        uint32_t al[4] = {olo[2*kc][0], olo[2*kc][1], olo[2*kc+1][0], olo[2*kc+1][1]};
#pragma unroll
        for (int p = 0; p < 8; p++) {
            int r = 16 * p + ((ln >> 4) << 3) + (ln & 7);
            int ch = 2 * kc + ((ln >> 3) & 1);
            uint32_t off = r * 256 + ((ch ^ (r & 7)) << 4);
            uint32_t wh[4], wl[4];
            ldsm4(wh, sbase + SMWH + off);
            ldsm4(wl, sbase + SMWL + off);
            mma16816(eacc[2*p],   ah, wh);
            mma16816(eacc[2*p+1], ah, wh + 2);
            mma16816(eacc[2*p],   ah, wl);
            mma16816(eacc[2*p+1], ah, wl + 2);
            mma16816(eacc[2*p],   al, wh);
            mma16816(eacc[2*p+1], al, wh + 2);
        }
    }

    // LeakyReLU + BN, scatter to stage [128o][132m] (reuses KV smem)
    __syncthreads();            // all warps done with last V tile before overwrite
    float* stage = (float*)(smc + SMKV);
    int r0 = 16 * w + (ln >> 2);
    int r1 = r0 + 8;
#pragma unroll
    for (int cb = 0; cb < 16; cb++) {
        int o0c = 8 * cb + 2 * (ln & 3);
        float s0 = g_sc[o0c],     b0 = g_bi[o0c];
        float s1 = g_sc[o0c + 1], b1 = g_bi[o0c + 1];
        float z0 = eacc[cb][0]; z0 = (z0 >= 0.f) ? z0 : 0.01f * z0;
        float z1 = eacc[cb][1]; z1 = (z1 >= 0.f) ? z1 : 0.01f * z1;
        float z2 = eacc[cb][2]; z2 = (z2 >= 0.f) ? z2 : 0.01f * z2;
        float z3 = eacc[cb][3]; z3 = (z3 >= 0.f) ? z3 : 0.01f * z3;
        stage[o0c * 132 + r0]       = z0 * s0 + b0;
        stage[(o0c + 1) * 132 + r0] = z1 * s1 + b1;
        stage[o0c * 132 + r1]       = z2 * s0 + b0;
        stage[(o0c + 1) * 132 + r1] = z3 * s1 + b1;
    }
    __syncthreads();

    // coalesced write: out[b][o][m0 + m]
    float* dst = out + ((size_t)b * OUT_) * M_ + m0;
    for (int idx = tid; idx < 128 * 32; idx += 256) {
        int o = idx >> 5, m4 = idx & 31;
        *(float4*)(dst + (size_t)o * M_ + 4 * m4) = *(float4*)(stage + o * 132 + 4 * m4);
    }
}

// ---------------------------------------------------------------------------
extern "C" void kernel_launch(void* const* d_in, const int* in_sizes, int n_in,
                              void* d_out, int out_size) {
    const float* input  = (const float*)d_in[0];
    const float* tg     = (const float*)d_in[1];
    const float* weight = (const float*)d_in[2];
    const float* gamma  = (const float*)d_in[3];
    const float* beta   = (const float*)d_in[4];
    const float* rmean  = (const float*)d_in[5];
    const float* rvar   = (const float*)d_in[6];
    float* out = (float*)d_out;

    const int prep_smem = (128 * 129 + 128) * (int)sizeof(float);
    cudaFuncSetAttribute(prep_all, cudaFuncAttributeMaxDynamicSharedMemorySize, prep_smem);
    cudaFuncSetAttribute(attn_mma_kernel, cudaFuncAttributeMaxDynamicSharedMemorySize, ATTN_SMEM);

    prep_all<<<1600, 256, prep_smem>>>(input, tg, weight, gamma, beta, rmean, rvar);
    attn_mma_kernel<<<B_ * (M_ / 128), 256, ATTN_SMEM>>>(out);
}